// round 16
// baseline (speedup 1.0000x reference)
#include <cuda_runtime.h>
#include <cuda_bf16.h>
#include <cstdint>
#include <math.h>

constexpr int B  = 2;
constexpr int S  = 2048;
constexpr int D  = 1024;
constexpr int H  = 16;
constexpr int DK = 64;
constexpr int BH = B * H;
constexpr int MP = B * S;

// ---------------------------------------------------------------------------
// Static device buffers
// ---------------------------------------------------------------------------
__device__ __nv_bfloat16 g_xq_h[MP * D], g_xq_l[MP * D];
__device__ __nv_bfloat16 g_xk_h[MP * D], g_xk_l[MP * D];
__device__ __nv_bfloat16 g_xv_h[MP * D], g_xv_l[MP * D];
__device__ __nv_bfloat16 g_wq_h[D * D], g_wq_l[D * D];
__device__ __nv_bfloat16 g_wk_h[D * D], g_wk_l[D * D];
__device__ __nv_bfloat16 g_wv_h[D * D], g_wv_l[D * D];
__device__ __nv_bfloat16 g_wo_h[D * D], g_wo_l[D * D];
__device__ __nv_bfloat16 g_q_h[BH * S * DK], g_q_l[BH * S * DK];
__device__ __nv_bfloat16 g_k_h[BH * S * DK], g_k_l[BH * S * DK];
__device__ __nv_bfloat16 g_v_h[BH * S * DK], g_v_l[BH * S * DK];
__device__ __nv_bfloat16 g_ctx_h[BH * S * DK], g_ctx_l[BH * S * DK];
__device__ float g_attn_scratch[(size_t)BH * S * S];
__device__ float g_out_scratch[MP * D];

// ---------------------------------------------------------------------------
// Helpers
// ---------------------------------------------------------------------------
__device__ __forceinline__ unsigned smem_u32(const void* p) {
    return (unsigned)__cvta_generic_to_shared(p);
}

#define CP16(dst_u32, src_ptr) \
    asm volatile("cp.async.cg.shared.global [%0], [%1], 16;" \
                 :: "r"(dst_u32), "l"(src_ptr) : "memory")
#define CP_COMMIT() asm volatile("cp.async.commit_group;" ::: "memory")
#define CP_WAIT1()  asm volatile("cp.async.wait_group 1;" ::: "memory")
#define CP_WAIT0()  asm volatile("cp.async.wait_group 0;" ::: "memory")

__device__ __forceinline__ void ldsm_x4(unsigned& r0, unsigned& r1,
                                        unsigned& r2, unsigned& r3, unsigned addr) {
    asm volatile("ldmatrix.sync.aligned.m8n8.x4.shared.b16 {%0,%1,%2,%3}, [%4];\n"
                 : "=r"(r0), "=r"(r1), "=r"(r2), "=r"(r3) : "r"(addr));
}
__device__ __forceinline__ void ldsm_x4_trans(unsigned& r0, unsigned& r1,
                                              unsigned& r2, unsigned& r3, unsigned addr) {
    asm volatile("ldmatrix.sync.aligned.m8n8.x4.trans.shared.b16 {%0,%1,%2,%3}, [%4];\n"
                 : "=r"(r0), "=r"(r1), "=r"(r2), "=r"(r3) : "r"(addr));
}
__device__ __forceinline__ void mma16816(float* c, const unsigned* a, const unsigned* b) {
    asm volatile(
        "mma.sync.aligned.m16n8k16.row.col.f32.bf16.bf16.f32 "
        "{%0,%1,%2,%3}, {%4,%5,%6,%7}, {%8,%9}, {%0,%1,%2,%3};\n"
        : "+f"(c[0]), "+f"(c[1]), "+f"(c[2]), "+f"(c[3])
        : "r"(a[0]), "r"(a[1]), "r"(a[2]), "r"(a[3]), "r"(b[0]), "r"(b[1]));
}

__device__ __forceinline__ void split_pack(float x, float y, unsigned& hi, unsigned& lo) {
    __nv_bfloat16 hx = __float2bfloat16(x);
    __nv_bfloat16 hy = __float2bfloat16(y);
    float rx = x - __bfloat162float(hx);
    float ry = y - __bfloat162float(hy);
    __nv_bfloat16 lx = __float2bfloat16(rx);
    __nv_bfloat16 ly = __float2bfloat16(ry);
    hi = (unsigned)__bfloat16_as_ushort(hx) | ((unsigned)__bfloat16_as_ushort(hy) << 16);
    lo = (unsigned)__bfloat16_as_ushort(lx) | ((unsigned)__bfloat16_as_ushort(ly) << 16);
}

// ===========================================================================
// Kernel 0: fp32 -> bf16 hi/lo conversion
// ===========================================================================
__global__ __launch_bounds__(256) void conv_kernel(const float* __restrict__ src,
                                                   __nv_bfloat16* __restrict__ h,
                                                   __nv_bfloat16* __restrict__ l,
                                                   int n) {
    int i = (blockIdx.x * 256 + threadIdx.x) * 4;
    if (i >= n) return;
    float4 v = *(const float4*)&src[i];
    unsigned h0, l0, h1, l1;
    split_pack(v.x, v.y, h0, l0);
    split_pack(v.z, v.w, h1, l1);
    *(uint2*)&h[i] = make_uint2(h0, h1);
    *(uint2*)&l[i] = make_uint2(l0, l1);
}

// ===========================================================================
// mm_gemm: 3-buffer cp.async pipeline, one barrier/stage, XOR swizzle (R14 WIN)
// ===========================================================================
#define MMT_ELEMS 4096
#define MM_SMEM_BYTES (3 * 4 * MMT_ELEMS * 2)

struct MMArgs {
    const __nv_bfloat16 *Agh, *Agl, *Bgh, *Bgl;
};

__device__ __forceinline__ void mm_load_stage(
    const MMArgs& a, unsigned sbase, int tid, int m0, int n0, int s, int buf, int mode) {
#pragma unroll
    for (int i = 0; i < 8; i++) {
        int c = i * 256 + tid;
        int tile = c >> 9;
        int w = c & 511;
        int row = w >> 2, c16 = w & 3;
        const __nv_bfloat16* src;
        size_t off;
        if (tile < 2) {
            src = tile ? a.Agl : a.Agh;
            int gr = m0 + row;
            if (mode == 0) {
                off = (size_t)gr * 1024 + s * 32;
            } else {
                int bb = gr >> 11, ss = gr & 2047;
                int k = s * 32;
                off = ((size_t)(bb * 16 + (k >> 6)) * 2048 + ss) * 64 + (k & 63);
            }
        } else {
            src = (tile == 3) ? a.Bgl : a.Bgh;
            off = (size_t)(n0 + row) * 1024 + s * 32;
        }
        int sc = c16 ^ ((row >> 1) & 3);
        unsigned d = sbase + ((buf * 4 + tile) * MMT_ELEMS + row * 32 + sc * 8) * 2;
        CP16(d, src + off + c16 * 8);
    }
}

__global__ __launch_bounds__(256) void mm_gemm(
    const __nv_bfloat16* __restrict__ Agh, const __nv_bfloat16* __restrict__ Agl,
    const __nv_bfloat16* __restrict__ Bgh, const __nv_bfloat16* __restrict__ Bgl,
    const float* __restrict__ bias,
    __nv_bfloat16* __restrict__ dst_h, __nv_bfloat16* __restrict__ dst_l,
    float* __restrict__ dst_f, int mode) {
    extern __shared__ __nv_bfloat16 sm[];
    const unsigned sbase = smem_u32(sm);
    const int tid = threadIdx.x, lane = tid & 31, wid = tid >> 5;
    const int wm = (wid & 1) * 64, wn = (wid >> 1) * 32;
    const int m0 = blockIdx.y * 128, n0 = blockIdx.x * 128;

    MMArgs args{Agh, Agl, Bgh, Bgl};

    float acc[4][4][4];
#pragma unroll
    for (int i = 0; i < 4; i++)
#pragma unroll
        for (int j = 0; j < 4; j++)
#pragma unroll
            for (int r = 0; r < 4; r++) acc[i][j][r] = 0.f;

    mm_load_stage(args, sbase, tid, m0, n0, 0, 0, mode); CP_COMMIT();
    mm_load_stage(args, sbase, tid, m0, n0, 1, 1, mode); CP_COMMIT();

    int buf = 0;
    for (int s = 0; s < 32; s++) {
        CP_WAIT1();
        __syncthreads();
        if (s + 2 < 32) {
            int nb3 = buf + 2; if (nb3 >= 3) nb3 -= 3;
            mm_load_stage(args, sbase, tid, m0, n0, s + 2, nb3, mode);
        }
        CP_COMMIT();

        const unsigned ah = sbase + (buf * 4 + 0) * MMT_ELEMS * 2;
        const unsigned al = sbase + (buf * 4 + 1) * MMT_ELEMS * 2;
        const unsigned bh = sbase + (buf * 4 + 2) * MMT_ELEMS * 2;
        const unsigned bl = sbase + (buf * 4 + 3) * MMT_ELEMS * 2;

#pragma unroll
        for (int kk = 0; kk < 32; kk += 16) {
            const int rb = (lane & 7) + ((lane >> 3) & 1) * 8;
            const int chunk = (kk >> 3) + ((lane >> 4) & 1);
            unsigned a_hi[4][4], a_lo[4][4];
#pragma unroll
            for (int mi = 0; mi < 4; mi++) {
                int row = wm + mi * 16 + rb;
                int sc = chunk ^ ((row >> 1) & 3);
                unsigned off = (row * 32 + sc * 8) * 2;
                ldsm_x4(a_hi[mi][0], a_hi[mi][1], a_hi[mi][2], a_hi[mi][3], ah + off);
                ldsm_x4(a_lo[mi][0], a_lo[mi][1], a_lo[mi][2], a_lo[mi][3], al + off);
            }
            unsigned b_hi[2][4], b_lo[2][4];
#pragma unroll
            for (int nb = 0; nb < 2; nb++) {
                int row = wn + nb * 16 + rb;
                int sc = chunk ^ ((row >> 1) & 3);
                unsigned off = (row * 32 + sc * 8) * 2;
                ldsm_x4(b_hi[nb][0], b_hi[nb][1], b_hi[nb][2], b_hi[nb][3], bh + off);
                ldsm_x4(b_lo[nb][0], b_lo[nb][1], b_lo[nb][2], b_lo[nb][3], bl + off);
            }
#pragma unroll
            for (int mi = 0; mi < 4; mi++)
#pragma unroll
                for (int nj = 0; nj < 4; nj++) {
                    int nb = nj >> 1, sel = nj & 1;
                    unsigned bh2[2] = {b_hi[nb][sel], b_hi[nb][sel + 2]};
                    unsigned bl2[2] = {b_lo[nb][sel], b_lo[nb][sel + 2]};
                    mma16816(acc[mi][nj], a_hi[mi], bh2);
                    mma16816(acc[mi][nj], a_hi[mi], bl2);
                    mma16816(acc[mi][nj], a_lo[mi], bh2);
                }
        }
        if (++buf == 3) buf = 0;
    }

    const int r0 = lane >> 2, c0 = (lane & 3) * 2;
#pragma unroll
    for (int mi = 0; mi < 4; mi++)
#pragma unroll
        for (int hf = 0; hf < 2; hf++) {
            int m = m0 + wm + mi * 16 + r0 + hf * 8;
            int bb = m >> 11, ss = m & 2047;
#pragma unroll
            for (int nj = 0; nj < 4; nj++) {
                int n = n0 + wn + nj * 8 + c0;
                float x = acc[mi][nj][hf * 2 + 0] + bias[n];
                float y = acc[mi][nj][hf * 2 + 1] + bias[n + 1];
                if (mode == 0) {
                    int hh = n >> 6, dd = n & 63;
                    unsigned hu, lu;
                    split_pack(x, y, hu, lu);
                    size_t o = ((size_t)(bb * 16 + hh) * 2048 + ss) * 64 + dd;
                    *(unsigned*)&dst_h[o] = hu;
                    *(unsigned*)&dst_l[o] = lu;
                } else {
                    *(float2*)&dst_f[(size_t)m * 1024 + n] = make_float2(x, y);
                }
            }
        }
}

// ===========================================================================
// scores (unchanged — writes raw scaled scores, lower triangle)
// ===========================================================================
#define SSTR 72
#define ST_ELEMS (128 * SSTR)
#define SC_SMEM_BYTES (4 * ST_ELEMS * 2)

__global__ __launch_bounds__(256) void scores_kernel(
    const __nv_bfloat16* __restrict__ qh, const __nv_bfloat16* __restrict__ ql,
    const __nv_bfloat16* __restrict__ kh, const __nv_bfloat16* __restrict__ kl,
    float* __restrict__ attn) {
    if (blockIdx.x > blockIdx.y) return;
    const bool full = (blockIdx.x < blockIdx.y);

    extern __shared__ __nv_bfloat16 sm[];
    const unsigned sbase = smem_u32(sm);
    const int tid = threadIdx.x, lane = tid & 31, wid = tid >> 5;
    const int wm = (wid & 1) * 64, wn = (wid >> 1) * 32;
    const int bh_ = blockIdx.z;
    const int i0 = blockIdx.y * 128, j0 = blockIdx.x * 128;
    const size_t basep = (size_t)bh_ * S * DK;

#pragma unroll
    for (int i = 0; i < 16; i++) {
        int c = i * 256 + tid;
        int tile = c >> 10;
        int w = c & 1023;
        int row = w >> 3, c16 = w & 7;
        const __nv_bfloat16* src = (tile == 0) ? qh : (tile == 1) ? ql
                                  : (tile == 2) ? kh : kl;
        int gr = (tile < 2 ? i0 : j0) + row;
        unsigned d = sbase + (tile * ST_ELEMS + row * SSTR + c16 * 8) * 2;
        CP16(d, src + basep + (size_t)gr * 64 + c16 * 8);
    }
    CP_COMMIT();

    float acc[4][4][4];
#pragma unroll
    for (int i = 0; i < 4; i++)
#pragma unroll
        for (int j = 0; j < 4; j++)
#pragma unroll
            for (int r = 0; r < 4; r++) acc[i][j][r] = 0.f;

    const unsigned ah  = sbase + 0 * ST_ELEMS * 2;
    const unsigned al  = sbase + 1 * ST_ELEMS * 2;
    const unsigned bhm = sbase + 2 * ST_ELEMS * 2;
    const unsigned blm = sbase + 3 * ST_ELEMS * 2;

    CP_WAIT0();
    __syncthreads();

#pragma unroll
    for (int kk = 0; kk < 64; kk += 16) {
        const int rb = (lane & 7) + ((lane >> 3) & 1) * 8;
        const int cA = kk + ((lane >> 4) & 1) * 8;
        unsigned a_hi[4][4], a_lo[4][4];
#pragma unroll
        for (int mi = 0; mi < 4; mi++) {
            unsigned off = ((wm + mi * 16 + rb) * SSTR + cA) * 2;
            ldsm_x4(a_hi[mi][0], a_hi[mi][1], a_hi[mi][2], a_hi[mi][3], ah + off);
            ldsm_x4(a_lo[mi][0], a_lo[mi][1], a_lo[mi][2], a_lo[mi][3], al + off);
        }
        unsigned b_hi[2][4], b_lo[2][4];
#pragma unroll
        for (int nb = 0; nb < 2; nb++) {
            unsigned off = ((wn + nb * 16 + rb) * SSTR + cA) * 2;
            ldsm_x4(b_hi[nb][0], b_hi[nb][1], b_hi[nb][2], b_hi[nb][3], bhm + off);
            ldsm_x4(b_lo[nb][0], b_lo[nb][1], b_lo[nb][2], b_lo[nb][3], blm + off);
        }
#pragma unroll
        for (int mi = 0; mi < 4; mi++)
#pragma unroll
            for (int nj = 0; nj < 4; nj++) {
                int nb = nj >> 1, sel = nj & 1;
                unsigned bh2[2] = {b_hi[nb][sel], b_hi[nb][sel + 2]};
                unsigned bl2[2] = {b_lo[nb][sel], b_lo[nb][sel + 2]};
                mma16816(acc[mi][nj], a_hi[mi], bh2);
                mma16816(acc[mi][nj], a_hi[mi], bl2);
                mma16816(acc[mi][nj], a_lo[mi], bh2);
            }
    }

    const int r0 = lane >> 2, c0 = (lane & 3) * 2;
#pragma unroll
    for (int mi = 0; mi < 4; mi++)
#pragma unroll
        for (int hf = 0; hf < 2; hf++) {
            int ii = i0 + wm + mi * 16 + r0 + hf * 8;
            float* row = attn + ((size_t)bh_ * S + ii) * S;
#pragma unroll
            for (int nj = 0; nj < 4; nj++) {
                int jj = j0 + wn + nj * 8 + c0;
                float vx = acc[mi][nj][hf * 2 + 0] * 0.125f;
                float vy = acc[mi][nj][hf * 2 + 1] * 0.125f;
                if (full) {
                    *(float2*)&row[jj] = make_float2(vx, vy);
                } else {
                    if (jj <= ii) row[jj] = vx;
                    if (jj + 1 <= ii) row[jj + 1] = vy;
                }
            }
        }
}

// ===========================================================================
// ctx = softmax + attn @ v  — per-block softmax PRE-PHASE (warp per row,
// no max-subtraction: scores ~ N(0,1) so exp is safe; validated R6),
// then the pipelined mma loop (R14 structure) reading the normalized rows.
// ===========================================================================
#define ASTR 40
#define VSTR 72
#define CTX_AH(b)  ((b) * 5120)
#define CTX_AL(b)  (10240 + (b) * 5120)
#define CTX_VH(b)  (20480 + (b) * 2304)
#define CTX_VL(b)  (25088 + (b) * 2304)
#define CTX_SMEM_BYTES (29696 * 2)

__global__ __launch_bounds__(256) void ctx_kernel(
    float* __restrict__ attn,
    const __nv_bfloat16* __restrict__ vh, const __nv_bfloat16* __restrict__ vl,
    __nv_bfloat16* __restrict__ ch, __nv_bfloat16* __restrict__ cl) {
    extern __shared__ __nv_bfloat16 dsm[];
    const unsigned base = smem_u32(dsm);

    const int tid = threadIdx.x, lane = tid & 31, wid = tid >> 5;
    const int wm = (wid & 3) * 32, wn = (wid >> 2) * 32;
    const int bh_ = blockIdx.z;
    const int i0 = (int)(gridDim.y - 1 - blockIdx.y) * 128;   // longest-first

    float* A = attn + (size_t)bh_ * S * S;
    const size_t basev = (size_t)bh_ * S * DK;
    const int kend = i0 + 128;

    // ---- softmax pre-phase: warp w handles rows i0 + w*16 .. +15 ----
    for (int r = 0; r < 16; r++) {
        const int i = i0 + wid * 16 + r;
        const int L = i + 1;
        float* row = A + (size_t)i * S;
        float s = 0.f;
        for (int c = lane * 4; c < kend; c += 128) {
            float4 v = *(const float4*)&row[c];
            if (c + 0 < L) s += __expf(v.x);
            if (c + 1 < L) s += __expf(v.y);
            if (c + 2 < L) s += __expf(v.z);
            if (c + 3 < L) s += __expf(v.w);
        }
#pragma unroll
        for (int o = 16; o; o >>= 1) s += __shfl_xor_sync(~0u, s, o);
        const float inv = 1.f / s;
        for (int c = lane * 4; c < kend; c += 128) {
            float4 v = *(const float4*)&row[c];
            float4 p;
            p.x = (c + 0 < L) ? __expf(v.x) * inv : 0.f;
            p.y = (c + 1 < L) ? __expf(v.y) * inv : 0.f;
            p.z = (c + 2 < L) ? __expf(v.z) * inv : 0.f;
            p.w = (c + 3 < L) ? __expf(v.w) * inv : 0.f;
            *(float4*)&row[c] = p;
        }
        const float4 z = make_float4(0.f, 0.f, 0.f, 0.f);
        for (int c = kend + lane * 4; c < S; c += 128)
            *(float4*)&row[c] = z;
    }
    __syncthreads();   // global writes visible block-wide before mma reads

    // ---- mma phase (R14 pipelined structure, unchanged arithmetic) ----
    float acc[2][4][4];
#pragma unroll
    for (int i = 0; i < 2; i++)
#pragma unroll
        for (int j = 0; j < 4; j++)
#pragma unroll
            for (int r = 0; r < 4; r++) acc[i][j][r] = 0.f;

    const int nit = kend / 32;

    float4 ar[4];
    uint4  vr[2];

    {
        const int k0 = 0;
#pragma unroll
        for (int q = 0; q < 4; q++) {
            int id = tid + q * 256;
            int row = id >> 3, col = (id & 7) * 4;
            ar[q] = *(const float4*)&A[(size_t)(i0 + row) * S + k0 + col];
        }
#pragma unroll
        for (int i = 0; i < 2; i++) {
            int c = tid + i * 256;
            int tile = c >> 8;
            int w = c & 255;
            int row = w >> 3, col16 = w & 7;
            const __nv_bfloat16* src = tile ? vl : vh;
            vr[i] = *(const uint4*)&src[basev + (size_t)(k0 + row) * 64 + col16 * 8];
        }
    }

    for (int it = 0; it < nit; it++) {
        const int b = it & 1;
        __nv_bfloat16* AhB = dsm + CTX_AH(b);
        __nv_bfloat16* AlB = dsm + CTX_AL(b);
        __nv_bfloat16* VhB = dsm + CTX_VH(b);
        __nv_bfloat16* VlB = dsm + CTX_VL(b);

#pragma unroll
        for (int q = 0; q < 4; q++) {
            int id = tid + q * 256;
            int row = id >> 3, col = (id & 7) * 4;
            unsigned h0, l0, h1, l1;
            split_pack(ar[q].x, ar[q].y, h0, l0);
            split_pack(ar[q].z, ar[q].w, h1, l1);
            *(unsigned*)&AhB[row * ASTR + col] = h0;
            *(unsigned*)&AhB[row * ASTR + col + 2] = h1;
            *(unsigned*)&AlB[row * ASTR + col] = l0;
            *(unsigned*)&AlB[row * ASTR + col + 2] = l1;
        }
#pragma unroll
        for (int i = 0; i < 2; i++) {
            int c = tid + i * 256;
            int tile = c >> 8;
            int w = c & 255;
            int row = w >> 3, col16 = w & 7;
            __nv_bfloat16* VB = tile ? VlB : VhB;
            *(uint4*)&VB[row * VSTR + col16 * 8] = vr[i];
        }

        if (it + 1 < nit) {
            const int k0 = (it + 1) * 32;
#pragma unroll
            for (int q = 0; q < 4; q++) {
                int id = tid + q * 256;
                int row = id >> 3, col = (id & 7) * 4;
                ar[q] = *(const float4*)&A[(size_t)(i0 + row) * S + k0 + col];
            }
#pragma unroll
            for (int i = 0; i < 2; i++) {
                int c = tid + i * 256;
                int tile = c >> 8;
                int w = c & 255;
                int row = w >> 3, col16 = w & 7;
                const __nv_bfloat16* src = tile ? vl : vh;
                vr[i] = *(const uint4*)&src[basev + (size_t)(k0 + row) * 64 + col16 * 8];
            }
        }

        __syncthreads();

        const unsigned ah  = base + CTX_AH(b) * 2;
        const unsigned al  = base + CTX_AL(b) * 2;
        const unsigned vhm = base + CTX_VH(b) * 2;
        const unsigned vlm = base + CTX_VL(b) * 2;

#pragma unroll
        for (int kk = 0; kk < 32; kk += 16) {
            const int rb = (lane & 7) + ((lane >> 3) & 1) * 8;
            const int cA = kk + ((lane >> 4) & 1) * 8;
            unsigned a_hi[2][4], a_lo[2][4];
#pragma unroll
            for (int mi = 0; mi < 2; mi++) {
                unsigned off = ((wm + mi * 16 + rb) * ASTR + cA) * 2;
                ldsm_x4(a_hi[mi][0], a_hi[mi][1], a_hi[mi][2], a_hi[mi][3], ah + off);
                ldsm_x4(a_lo[mi][0], a_lo[mi][1], a_lo[mi][2], a_lo[mi][3], al + off);
            }
            const int kr = kk + (lane & 7) + ((lane >> 3) & 1) * 8;
            unsigned b_hi[2][4], b_lo[2][4];
#pragma unroll
            for (int nb = 0; nb < 2; nb++) {
                int nc = wn + nb * 16 + ((lane >> 4) & 1) * 8;
                unsigned off = (kr * VSTR + nc) * 2;
                ldsm_x4_trans(b_hi[nb][0], b_hi[nb][1], b_hi[nb][2], b_hi[nb][3], vhm + off);
                ldsm_x4_trans(b_lo[nb][0], b_lo[nb][1], b_lo[nb][2], b_lo[nb][3], vlm + off);
            }
#pragma unroll
            for (int mi = 0; mi < 2; mi++)
#pragma unroll
                for (int nj = 0; nj < 4; nj++) {
                    int nb = nj >> 1, sel = nj & 1;
                    unsigned bh2[2] = {b_hi[nb][sel * 2], b_hi[nb][sel * 2 + 1]};
                    unsigned bl2[2] = {b_lo[nb][sel * 2], b_lo[nb][sel * 2 + 1]};
                    mma16816(acc[mi][nj], a_hi[mi], bh2);
                    mma16816(acc[mi][nj], a_hi[mi], bl2);
                    mma16816(acc[mi][nj], a_lo[mi], bh2);
                }
        }
    }

    const int r0 = lane >> 2, c0 = (lane & 3) * 2;
#pragma unroll
    for (int mi = 0; mi < 2; mi++)
#pragma unroll
        for (int hf = 0; hf < 2; hf++) {
            int ii = i0 + wm + mi * 16 + r0 + hf * 8;
#pragma unroll
            for (int nj = 0; nj < 4; nj++) {
                int dd = wn + nj * 8 + c0;
                float x = acc[mi][nj][hf * 2 + 0];
                float y = acc[mi][nj][hf * 2 + 1];
                unsigned hu, lu;
                split_pack(x, y, hu, lu);
                size_t o = ((size_t)bh_ * S + ii) * DK + dd;
                *(unsigned*)&ch[o] = hu;
                *(unsigned*)&cl[o] = lu;
            }
        }
}

// ---------------------------------------------------------------------------
// Launch (softmax kernel removed)
// ---------------------------------------------------------------------------
extern "C" void kernel_launch(void* const* d_in, const int* in_sizes, int n_in,
                              void* d_out, int out_size) {
    const float* Q  = (const float*)d_in[0];
    const float* K  = (const float*)d_in[1];
    const float* V  = (const float*)d_in[2];
    const float* Wq = (const float*)d_in[4];
    const float* bq = (const float*)d_in[5];
    const float* Wk = (const float*)d_in[6];
    const float* bk = (const float*)d_in[7];
    const float* Wv = (const float*)d_in[8];
    const float* bv = (const float*)d_in[9];
    const float* Wo = (const float*)d_in[10];
    const float* bo = (const float*)d_in[11];

    cudaFuncSetAttribute(mm_gemm, cudaFuncAttributeMaxDynamicSharedMemorySize,
                         MM_SMEM_BYTES);
    cudaFuncSetAttribute(scores_kernel, cudaFuncAttributeMaxDynamicSharedMemorySize,
                         SC_SMEM_BYTES);
    cudaFuncSetAttribute(ctx_kernel, cudaFuncAttributeMaxDynamicSharedMemorySize,
                         CTX_SMEM_BYTES);

#define SYM(p, s) cudaGetSymbolAddress((void**)&p, s)
    __nv_bfloat16 *xqh, *xql, *xkh, *xkl, *xvh, *xvl;
    __nv_bfloat16 *wqh, *wql, *wkh, *wkl, *wvh, *wvl, *woh, *wol;
    __nv_bfloat16 *qh, *ql, *kh, *kl, *vh, *vl, *ch, *cl;
    SYM(xqh, g_xq_h); SYM(xql, g_xq_l); SYM(xkh, g_xk_h); SYM(xkl, g_xk_l);
    SYM(xvh, g_xv_h); SYM(xvl, g_xv_l);
    SYM(wqh, g_wq_h); SYM(wql, g_wq_l); SYM(wkh, g_wk_h); SYM(wkl, g_wk_l);
    SYM(wvh, g_wv_h); SYM(wvl, g_wv_l); SYM(woh, g_wo_h); SYM(wol, g_wo_l);
    SYM(qh, g_q_h); SYM(ql, g_q_l); SYM(kh, g_k_h); SYM(kl, g_k_l);
    SYM(vh, g_v_h); SYM(vl, g_v_l); SYM(ch, g_ctx_h); SYM(cl, g_ctx_l);

    const size_t OUT_MAIN = (size_t)B * S * D;
    const size_t OUT_ATTN = (size_t)BH * S * S;
    float* outp;
    float* attnp;
    if ((size_t)out_size == OUT_MAIN + OUT_ATTN) {
        outp  = (float*)d_out;
        attnp = (float*)d_out + OUT_MAIN;
    } else if ((size_t)out_size == OUT_ATTN) {
        attnp = (float*)d_out;
        cudaGetSymbolAddress((void**)&outp, g_out_scratch);
    } else {
        outp = (float*)d_out;
        cudaGetSymbolAddress((void**)&attnp, g_attn_scratch);
    }

    const int NX = MP * D, NW = D * D;
    conv_kernel<<<NX / 1024, 256>>>(Q, xqh, xql, NX);
    conv_kernel<<<NX / 1024, 256>>>(K, xkh, xkl, NX);
    conv_kernel<<<NX / 1024, 256>>>(V, xvh, xvl, NX);
    conv_kernel<<<NW / 1024, 256>>>(Wq, wqh, wql, NW);
    conv_kernel<<<NW / 1024, 256>>>(Wk, wkh, wkl, NW);
    conv_kernel<<<NW / 1024, 256>>>(Wv, wvh, wvl, NW);
    conv_kernel<<<NW / 1024, 256>>>(Wo, woh, wol, NW);

    dim3 gproj(D / 128, MP / 128);
    mm_gemm<<<gproj, 256, MM_SMEM_BYTES>>>(xqh, xql, wqh, wql, bq, qh, ql, nullptr, 0);
    mm_gemm<<<gproj, 256, MM_SMEM_BYTES>>>(xkh, xkl, wkh, wkl, bk, kh, kl, nullptr, 0);
    mm_gemm<<<gproj, 256, MM_SMEM_BYTES>>>(xvh, xvl, wvh, wvl, bv, vh, vl, nullptr, 0);

    scores_kernel<<<dim3(S / 128, S / 128, BH), 256, SC_SMEM_BYTES>>>(qh, ql, kh, kl, attnp);

    ctx_kernel<<<dim3(1, S / 128, BH), 256, CTX_SMEM_BYTES>>>(attnp, vh, vl, ch, cl);

    mm_gemm<<<gproj, 256, MM_SMEM_BYTES>>>(ch, cl, woh, wol, bo, nullptr, nullptr, outp, 1);
}

// round 17
// speedup vs baseline: 1.1180x; 1.1180x over previous
#include <cuda_runtime.h>
#include <cuda_bf16.h>
#include <cstdint>
#include <math.h>

constexpr int B  = 2;
constexpr int S  = 2048;
constexpr int D  = 1024;
constexpr int H  = 16;
constexpr int DK = 64;
constexpr int BH = B * H;
constexpr int MP = B * S;

// ---------------------------------------------------------------------------
// Static device buffers
// ---------------------------------------------------------------------------
__device__ __nv_bfloat16 g_xq_h[MP * D], g_xq_l[MP * D];
__device__ __nv_bfloat16 g_xk_h[MP * D], g_xk_l[MP * D];
__device__ __nv_bfloat16 g_xv_h[MP * D], g_xv_l[MP * D];
__device__ __nv_bfloat16 g_wq_h[D * D], g_wq_l[D * D];
__device__ __nv_bfloat16 g_wk_h[D * D], g_wk_l[D * D];
__device__ __nv_bfloat16 g_wv_h[D * D], g_wv_l[D * D];
__device__ __nv_bfloat16 g_wo_h[D * D], g_wo_l[D * D];
__device__ __nv_bfloat16 g_q_h[BH * S * DK], g_q_l[BH * S * DK];
__device__ __nv_bfloat16 g_k_h[BH * S * DK], g_k_l[BH * S * DK];
__device__ __nv_bfloat16 g_v_h[BH * S * DK], g_v_l[BH * S * DK];
__device__ __nv_bfloat16 g_ctx_h[BH * S * DK], g_ctx_l[BH * S * DK];
__device__ float g_attn_scratch[(size_t)BH * S * S];
__device__ float g_out_scratch[MP * D];

// ---------------------------------------------------------------------------
// Helpers
// ---------------------------------------------------------------------------
__device__ __forceinline__ unsigned smem_u32(const void* p) {
    return (unsigned)__cvta_generic_to_shared(p);
}

#define CP16(dst_u32, src_ptr) \
    asm volatile("cp.async.cg.shared.global [%0], [%1], 16;" \
                 :: "r"(dst_u32), "l"(src_ptr) : "memory")
#define CP_COMMIT() asm volatile("cp.async.commit_group;" ::: "memory")
#define CP_WAIT1()  asm volatile("cp.async.wait_group 1;" ::: "memory")
#define CP_WAIT0()  asm volatile("cp.async.wait_group 0;" ::: "memory")

__device__ __forceinline__ void ldsm_x4(unsigned& r0, unsigned& r1,
                                        unsigned& r2, unsigned& r3, unsigned addr) {
    asm volatile("ldmatrix.sync.aligned.m8n8.x4.shared.b16 {%0,%1,%2,%3}, [%4];\n"
                 : "=r"(r0), "=r"(r1), "=r"(r2), "=r"(r3) : "r"(addr));
}
__device__ __forceinline__ void ldsm_x4_trans(unsigned& r0, unsigned& r1,
                                              unsigned& r2, unsigned& r3, unsigned addr) {
    asm volatile("ldmatrix.sync.aligned.m8n8.x4.trans.shared.b16 {%0,%1,%2,%3}, [%4];\n"
                 : "=r"(r0), "=r"(r1), "=r"(r2), "=r"(r3) : "r"(addr));
}
__device__ __forceinline__ void mma16816(float* c, const unsigned* a, const unsigned* b) {
    asm volatile(
        "mma.sync.aligned.m16n8k16.row.col.f32.bf16.bf16.f32 "
        "{%0,%1,%2,%3}, {%4,%5,%6,%7}, {%8,%9}, {%0,%1,%2,%3};\n"
        : "+f"(c[0]), "+f"(c[1]), "+f"(c[2]), "+f"(c[3])
        : "r"(a[0]), "r"(a[1]), "r"(a[2]), "r"(a[3]), "r"(b[0]), "r"(b[1]));
}

__device__ __forceinline__ void split_pack(float x, float y, unsigned& hi, unsigned& lo) {
    __nv_bfloat16 hx = __float2bfloat16(x);
    __nv_bfloat16 hy = __float2bfloat16(y);
    float rx = x - __bfloat162float(hx);
    float ry = y - __bfloat162float(hy);
    __nv_bfloat16 lx = __float2bfloat16(rx);
    __nv_bfloat16 ly = __float2bfloat16(ry);
    hi = (unsigned)__bfloat16_as_ushort(hx) | ((unsigned)__bfloat16_as_ushort(hy) << 16);
    lo = (unsigned)__bfloat16_as_ushort(lx) | ((unsigned)__bfloat16_as_ushort(ly) << 16);
}

// ===========================================================================
// Kernel 0: fp32 -> bf16 hi/lo conversion
// ===========================================================================
__global__ __launch_bounds__(256) void conv_kernel(const float* __restrict__ src,
                                                   __nv_bfloat16* __restrict__ h,
                                                   __nv_bfloat16* __restrict__ l,
                                                   int n) {
    int i = (blockIdx.x * 256 + threadIdx.x) * 4;
    if (i >= n) return;
    float4 v = *(const float4*)&src[i];
    unsigned h0, l0, h1, l1;
    split_pack(v.x, v.y, h0, l0);
    split_pack(v.z, v.w, h1, l1);
    *(uint2*)&h[i] = make_uint2(h0, h1);
    *(uint2*)&l[i] = make_uint2(l0, l1);
}

// ===========================================================================
// mm_gemm: 3-buffer pipeline, 1 barrier/stage, XOR swizzle (R14 WIN)
// + pass-major mma ordering (hh all, hl all, lh all) — per-acc order preserved
// ===========================================================================
#define MMT_ELEMS 4096
#define MM_SMEM_BYTES (3 * 4 * MMT_ELEMS * 2)

struct MMArgs {
    const __nv_bfloat16 *Agh, *Agl, *Bgh, *Bgl;
};

__device__ __forceinline__ void mm_load_stage(
    const MMArgs& a, unsigned sbase, int tid, int m0, int n0, int s, int buf, int mode) {
#pragma unroll
    for (int i = 0; i < 8; i++) {
        int c = i * 256 + tid;
        int tile = c >> 9;
        int w = c & 511;
        int row = w >> 2, c16 = w & 3;
        const __nv_bfloat16* src;
        size_t off;
        if (tile < 2) {
            src = tile ? a.Agl : a.Agh;
            int gr = m0 + row;
            if (mode == 0) {
                off = (size_t)gr * 1024 + s * 32;
            } else {
                int bb = gr >> 11, ss = gr & 2047;
                int k = s * 32;
                off = ((size_t)(bb * 16 + (k >> 6)) * 2048 + ss) * 64 + (k & 63);
            }
        } else {
            src = (tile == 3) ? a.Bgl : a.Bgh;
            off = (size_t)(n0 + row) * 1024 + s * 32;
        }
        int sc = c16 ^ ((row >> 1) & 3);
        unsigned d = sbase + ((buf * 4 + tile) * MMT_ELEMS + row * 32 + sc * 8) * 2;
        CP16(d, src + off + c16 * 8);
    }
}

__global__ __launch_bounds__(256) void mm_gemm(
    const __nv_bfloat16* __restrict__ Agh, const __nv_bfloat16* __restrict__ Agl,
    const __nv_bfloat16* __restrict__ Bgh, const __nv_bfloat16* __restrict__ Bgl,
    const float* __restrict__ bias,
    __nv_bfloat16* __restrict__ dst_h, __nv_bfloat16* __restrict__ dst_l,
    float* __restrict__ dst_f, int mode) {
    extern __shared__ __nv_bfloat16 sm[];
    const unsigned sbase = smem_u32(sm);
    const int tid = threadIdx.x, lane = tid & 31, wid = tid >> 5;
    const int wm = (wid & 1) * 64, wn = (wid >> 1) * 32;
    const int m0 = blockIdx.y * 128, n0 = blockIdx.x * 128;

    MMArgs args{Agh, Agl, Bgh, Bgl};

    float acc[4][4][4];
#pragma unroll
    for (int i = 0; i < 4; i++)
#pragma unroll
        for (int j = 0; j < 4; j++)
#pragma unroll
            for (int r = 0; r < 4; r++) acc[i][j][r] = 0.f;

    mm_load_stage(args, sbase, tid, m0, n0, 0, 0, mode); CP_COMMIT();
    mm_load_stage(args, sbase, tid, m0, n0, 1, 1, mode); CP_COMMIT();

    int buf = 0;
    for (int s = 0; s < 32; s++) {
        CP_WAIT1();
        __syncthreads();
        if (s + 2 < 32) {
            int nb3 = buf + 2; if (nb3 >= 3) nb3 -= 3;
            mm_load_stage(args, sbase, tid, m0, n0, s + 2, nb3, mode);
        }
        CP_COMMIT();

        const unsigned ah = sbase + (buf * 4 + 0) * MMT_ELEMS * 2;
        const unsigned al = sbase + (buf * 4 + 1) * MMT_ELEMS * 2;
        const unsigned bh = sbase + (buf * 4 + 2) * MMT_ELEMS * 2;
        const unsigned bl = sbase + (buf * 4 + 3) * MMT_ELEMS * 2;

#pragma unroll
        for (int kk = 0; kk < 32; kk += 16) {
            const int rb = (lane & 7) + ((lane >> 3) & 1) * 8;
            const int chunk = (kk >> 3) + ((lane >> 4) & 1);
            unsigned a_hi[4][4], a_lo[4][4];
#pragma unroll
            for (int mi = 0; mi < 4; mi++) {
                int row = wm + mi * 16 + rb;
                int sc = chunk ^ ((row >> 1) & 3);
                unsigned off = (row * 32 + sc * 8) * 2;
                ldsm_x4(a_hi[mi][0], a_hi[mi][1], a_hi[mi][2], a_hi[mi][3], ah + off);
                ldsm_x4(a_lo[mi][0], a_lo[mi][1], a_lo[mi][2], a_lo[mi][3], al + off);
            }
            unsigned b_hi[2][4], b_lo[2][4];
#pragma unroll
            for (int nb = 0; nb < 2; nb++) {
                int row = wn + nb * 16 + rb;
                int sc = chunk ^ ((row >> 1) & 3);
                unsigned off = (row * 32 + sc * 8) * 2;
                ldsm_x4(b_hi[nb][0], b_hi[nb][1], b_hi[nb][2], b_hi[nb][3], bh + off);
                ldsm_x4(b_lo[nb][0], b_lo[nb][1], b_lo[nb][2], b_lo[nb][3], bl + off);
            }
            // pass-major ordering: all hh, then all hl, then all lh
#pragma unroll
            for (int mi = 0; mi < 4; mi++)
#pragma unroll
                for (int nj = 0; nj < 4; nj++) {
                    int nb = nj >> 1, sel = nj & 1;
                    unsigned bh2[2] = {b_hi[nb][sel], b_hi[nb][sel + 2]};
                    mma16816(acc[mi][nj], a_hi[mi], bh2);
                }
#pragma unroll
            for (int mi = 0; mi < 4; mi++)
#pragma unroll
                for (int nj = 0; nj < 4; nj++) {
                    int nb = nj >> 1, sel = nj & 1;
                    unsigned bl2[2] = {b_lo[nb][sel], b_lo[nb][sel + 2]};
                    mma16816(acc[mi][nj], a_hi[mi], bl2);
                }
#pragma unroll
            for (int mi = 0; mi < 4; mi++)
#pragma unroll
                for (int nj = 0; nj < 4; nj++) {
                    int nb = nj >> 1, sel = nj & 1;
                    unsigned bh2[2] = {b_hi[nb][sel], b_hi[nb][sel + 2]};
                    mma16816(acc[mi][nj], a_lo[mi], bh2);
                }
        }
        if (++buf == 3) buf = 0;
    }

    const int r0 = lane >> 2, c0 = (lane & 3) * 2;
#pragma unroll
    for (int mi = 0; mi < 4; mi++)
#pragma unroll
        for (int hf = 0; hf < 2; hf++) {
            int m = m0 + wm + mi * 16 + r0 + hf * 8;
            int bb = m >> 11, ss = m & 2047;
#pragma unroll
            for (int nj = 0; nj < 4; nj++) {
                int n = n0 + wn + nj * 8 + c0;
                float x = acc[mi][nj][hf * 2 + 0] + bias[n];
                float y = acc[mi][nj][hf * 2 + 1] + bias[n + 1];
                if (mode == 0) {
                    int hh = n >> 6, dd = n & 63;
                    unsigned hu, lu;
                    split_pack(x, y, hu, lu);
                    size_t o = ((size_t)(bb * 16 + hh) * 2048 + ss) * 64 + dd;
                    *(unsigned*)&dst_h[o] = hu;
                    *(unsigned*)&dst_l[o] = lu;
                } else {
                    *(float2*)&dst_f[(size_t)m * 1024 + n] = make_float2(x, y);
                }
            }
        }
}

// ===========================================================================
// scores — pass-major mma ordering, otherwise 752us config
// ===========================================================================
#define SSTR 72
#define ST_ELEMS (128 * SSTR)
#define SC_SMEM_BYTES (4 * ST_ELEMS * 2)

__global__ __launch_bounds__(256) void scores_kernel(
    const __nv_bfloat16* __restrict__ qh, const __nv_bfloat16* __restrict__ ql,
    const __nv_bfloat16* __restrict__ kh, const __nv_bfloat16* __restrict__ kl,
    float* __restrict__ attn) {
    if (blockIdx.x > blockIdx.y) return;
    const bool full = (blockIdx.x < blockIdx.y);

    extern __shared__ __nv_bfloat16 sm[];
    const unsigned sbase = smem_u32(sm);
    const int tid = threadIdx.x, lane = tid & 31, wid = tid >> 5;
    const int wm = (wid & 1) * 64, wn = (wid >> 1) * 32;
    const int bh_ = blockIdx.z;
    const int i0 = blockIdx.y * 128, j0 = blockIdx.x * 128;
    const size_t basep = (size_t)bh_ * S * DK;

#pragma unroll
    for (int i = 0; i < 16; i++) {
        int c = i * 256 + tid;
        int tile = c >> 10;
        int w = c & 1023;
        int row = w >> 3, c16 = w & 7;
        const __nv_bfloat16* src = (tile == 0) ? qh : (tile == 1) ? ql
                                  : (tile == 2) ? kh : kl;
        int gr = (tile < 2 ? i0 : j0) + row;
        unsigned d = sbase + (tile * ST_ELEMS + row * SSTR + c16 * 8) * 2;
        CP16(d, src + basep + (size_t)gr * 64 + c16 * 8);
    }
    CP_COMMIT();

    float acc[4][4][4];
#pragma unroll
    for (int i = 0; i < 4; i++)
#pragma unroll
        for (int j = 0; j < 4; j++)
#pragma unroll
            for (int r = 0; r < 4; r++) acc[i][j][r] = 0.f;

    const unsigned ah  = sbase + 0 * ST_ELEMS * 2;
    const unsigned al  = sbase + 1 * ST_ELEMS * 2;
    const unsigned bhm = sbase + 2 * ST_ELEMS * 2;
    const unsigned blm = sbase + 3 * ST_ELEMS * 2;

    CP_WAIT0();
    __syncthreads();

#pragma unroll
    for (int kk = 0; kk < 64; kk += 16) {
        const int rb = (lane & 7) + ((lane >> 3) & 1) * 8;
        const int cA = kk + ((lane >> 4) & 1) * 8;
        unsigned a_hi[4][4], a_lo[4][4];
#pragma unroll
        for (int mi = 0; mi < 4; mi++) {
            unsigned off = ((wm + mi * 16 + rb) * SSTR + cA) * 2;
            ldsm_x4(a_hi[mi][0], a_hi[mi][1], a_hi[mi][2], a_hi[mi][3], ah + off);
            ldsm_x4(a_lo[mi][0], a_lo[mi][1], a_lo[mi][2], a_lo[mi][3], al + off);
        }
        unsigned b_hi[2][4], b_lo[2][4];
#pragma unroll
        for (int nb = 0; nb < 2; nb++) {
            unsigned off = ((wn + nb * 16 + rb) * SSTR + cA) * 2;
            ldsm_x4(b_hi[nb][0], b_hi[nb][1], b_hi[nb][2], b_hi[nb][3], bhm + off);
            ldsm_x4(b_lo[nb][0], b_lo[nb][1], b_lo[nb][2], b_lo[nb][3], blm + off);
        }
#pragma unroll
        for (int mi = 0; mi < 4; mi++)
#pragma unroll
            for (int nj = 0; nj < 4; nj++) {
                int nb = nj >> 1, sel = nj & 1;
                unsigned bh2[2] = {b_hi[nb][sel], b_hi[nb][sel + 2]};
                mma16816(acc[mi][nj], a_hi[mi], bh2);
            }
#pragma unroll
        for (int mi = 0; mi < 4; mi++)
#pragma unroll
            for (int nj = 0; nj < 4; nj++) {
                int nb = nj >> 1, sel = nj & 1;
                unsigned bl2[2] = {b_lo[nb][sel], b_lo[nb][sel + 2]};
                mma16816(acc[mi][nj], a_hi[mi], bl2);
            }
#pragma unroll
        for (int mi = 0; mi < 4; mi++)
#pragma unroll
            for (int nj = 0; nj < 4; nj++) {
                int nb = nj >> 1, sel = nj & 1;
                unsigned bh2[2] = {b_hi[nb][sel], b_hi[nb][sel + 2]};
                mma16816(acc[mi][nj], a_lo[mi], bh2);
            }
    }

    const int r0 = lane >> 2, c0 = (lane & 3) * 2;
#pragma unroll
    for (int mi = 0; mi < 4; mi++)
#pragma unroll
        for (int hf = 0; hf < 2; hf++) {
            int ii = i0 + wm + mi * 16 + r0 + hf * 8;
            float* row = attn + ((size_t)bh_ * S + ii) * S;
#pragma unroll
            for (int nj = 0; nj < 4; nj++) {
                int jj = j0 + wn + nj * 8 + c0;
                float vx = acc[mi][nj][hf * 2 + 0] * 0.125f;
                float vy = acc[mi][nj][hf * 2 + 1] * 0.125f;
                if (full) {
                    *(float2*)&row[jj] = make_float2(vx, vy);
                } else {
                    if (jj <= ii) row[jj] = vx;
                    if (jj + 1 <= ii) row[jj + 1] = vy;
                }
            }
        }
}

// ===========================================================================
// softmax (R3 exact — standalone, frozen)
// ===========================================================================
__global__ __launch_bounds__(256) void softmax_kernel(float* __restrict__ attn) {
    const int i = blockIdx.x, bh_ = blockIdx.y;
    float* row = attn + ((size_t)bh_ * S + i) * S;
    const int L = i + 1;
    const int t = threadIdx.x;

    __shared__ float red[8];

    float v[8];
    float mx = -3.4e38f;
#pragma unroll
    for (int q = 0; q < 8; q++) {
        int j = t + q * 256;
        v[q] = (j < L) ? row[j] : -3.4e38f;
        mx = fmaxf(mx, v[q]);
    }
#pragma unroll
    for (int o = 16; o; o >>= 1) mx = fmaxf(mx, __shfl_xor_sync(~0u, mx, o));
    if ((t & 31) == 0) red[t >> 5] = mx;
    __syncthreads();
    float m = fmaxf(fmaxf(fmaxf(red[0], red[1]), fmaxf(red[2], red[3])),
                    fmaxf(fmaxf(red[4], red[5]), fmaxf(red[6], red[7])));
    __syncthreads();

    float sum = 0.f;
#pragma unroll
    for (int q = 0; q < 8; q++) {
        float e = __expf(v[q] - m);
        v[q] = e;
        sum += e;
    }
#pragma unroll
    for (int o = 16; o; o >>= 1) sum += __shfl_xor_sync(~0u, sum, o);
    if ((t & 31) == 0) red[t >> 5] = sum;
    __syncthreads();
    float tot = red[0] + red[1] + red[2] + red[3] + red[4] + red[5] + red[6] + red[7];
    float inv = 1.f / tot;

#pragma unroll
    for (int q = 0; q < 8; q++) {
        int j = t + q * 256;
        row[j] = v[q] * inv;
    }
}

// ===========================================================================
// ctx = attn @ v — pipelined + longest-first + pass-major mma ordering
// ===========================================================================
#define ASTR 40
#define VSTR 72
#define CTX_AH(b)  ((b) * 5120)
#define CTX_AL(b)  (10240 + (b) * 5120)
#define CTX_VH(b)  (20480 + (b) * 2304)
#define CTX_VL(b)  (25088 + (b) * 2304)
#define CTX_SMEM_BYTES (29696 * 2)

__global__ __launch_bounds__(256) void ctx_kernel(
    const float* __restrict__ attn,
    const __nv_bfloat16* __restrict__ vh, const __nv_bfloat16* __restrict__ vl,
    __nv_bfloat16* __restrict__ ch, __nv_bfloat16* __restrict__ cl) {
    extern __shared__ __nv_bfloat16 dsm[];
    const unsigned base = smem_u32(dsm);

    const int tid = threadIdx.x, lane = tid & 31, wid = tid >> 5;
    const int wm = (wid & 3) * 32, wn = (wid >> 2) * 32;
    const int bh_ = blockIdx.z;
    const int i0 = (int)(gridDim.y - 1 - blockIdx.y) * 128;

    const float* A = attn + (size_t)bh_ * S * S;
    const size_t basev = (size_t)bh_ * S * DK;

    float acc[2][4][4];
#pragma unroll
    for (int i = 0; i < 2; i++)
#pragma unroll
        for (int j = 0; j < 4; j++)
#pragma unroll
            for (int r = 0; r < 4; r++) acc[i][j][r] = 0.f;

    const int nit = (i0 + 128) / 32;

    float4 ar[4];
    uint4  vr[2];

    {
        const int k0 = 0;
#pragma unroll
        for (int q = 0; q < 4; q++) {
            int id = tid + q * 256;
            int row = id >> 3, col = (id & 7) * 4;
            ar[q] = *(const float4*)&A[(size_t)(i0 + row) * S + k0 + col];
        }
#pragma unroll
        for (int i = 0; i < 2; i++) {
            int c = tid + i * 256;
            int tile = c >> 8;
            int w = c & 255;
            int row = w >> 3, col16 = w & 7;
            const __nv_bfloat16* src = tile ? vl : vh;
            vr[i] = *(const uint4*)&src[basev + (size_t)(k0 + row) * 64 + col16 * 8];
        }
    }

    for (int it = 0; it < nit; it++) {
        const int b = it & 1;
        __nv_bfloat16* AhB = dsm + CTX_AH(b);
        __nv_bfloat16* AlB = dsm + CTX_AL(b);
        __nv_bfloat16* VhB = dsm + CTX_VH(b);
        __nv_bfloat16* VlB = dsm + CTX_VL(b);

#pragma unroll
        for (int q = 0; q < 4; q++) {
            int id = tid + q * 256;
            int row = id >> 3, col = (id & 7) * 4;
            unsigned h0, l0, h1, l1;
            split_pack(ar[q].x, ar[q].y, h0, l0);
            split_pack(ar[q].z, ar[q].w, h1, l1);
            *(unsigned*)&AhB[row * ASTR + col] = h0;
            *(unsigned*)&AhB[row * ASTR + col + 2] = h1;
            *(unsigned*)&AlB[row * ASTR + col] = l0;
            *(unsigned*)&AlB[row * ASTR + col + 2] = l1;
        }
#pragma unroll
        for (int i = 0; i < 2; i++) {
            int c = tid + i * 256;
            int tile = c >> 8;
            int w = c & 255;
            int row = w >> 3, col16 = w & 7;
            __nv_bfloat16* VB = tile ? VlB : VhB;
            *(uint4*)&VB[row * VSTR + col16 * 8] = vr[i];
        }

        if (it + 1 < nit) {
            const int k0 = (it + 1) * 32;
#pragma unroll
            for (int q = 0; q < 4; q++) {
                int id = tid + q * 256;
                int row = id >> 3, col = (id & 7) * 4;
                ar[q] = *(const float4*)&A[(size_t)(i0 + row) * S + k0 + col];
            }
#pragma unroll
            for (int i = 0; i < 2; i++) {
                int c = tid + i * 256;
                int tile = c >> 8;
                int w = c & 255;
                int row = w >> 3, col16 = w & 7;
                const __nv_bfloat16* src = tile ? vl : vh;
                vr[i] = *(const uint4*)&src[basev + (size_t)(k0 + row) * 64 + col16 * 8];
            }
        }

        __syncthreads();

        const unsigned ah  = base + CTX_AH(b) * 2;
        const unsigned al  = base + CTX_AL(b) * 2;
        const unsigned vhm = base + CTX_VH(b) * 2;
        const unsigned vlm = base + CTX_VL(b) * 2;

#pragma unroll
        for (int kk = 0; kk < 32; kk += 16) {
            const int rb = (lane & 7) + ((lane >> 3) & 1) * 8;
            const int cA = kk + ((lane >> 4) & 1) * 8;
            unsigned a_hi[2][4], a_lo[2][4];
#pragma unroll
            for (int mi = 0; mi < 2; mi++) {
                unsigned off = ((wm + mi * 16 + rb) * ASTR + cA) * 2;
                ldsm_x4(a_hi[mi][0], a_hi[mi][1], a_hi[mi][2], a_hi[mi][3], ah + off);
                ldsm_x4(a_lo[mi][0], a_lo[mi][1], a_lo[mi][2], a_lo[mi][3], al + off);
            }
            const int kr = kk + (lane & 7) + ((lane >> 3) & 1) * 8;
            unsigned b_hi[2][4], b_lo[2][4];
#pragma unroll
            for (int nb = 0; nb < 2; nb++) {
                int nc = wn + nb * 16 + ((lane >> 4) & 1) * 8;
                unsigned off = (kr * VSTR + nc) * 2;
                ldsm_x4_trans(b_hi[nb][0], b_hi[nb][1], b_hi[nb][2], b_hi[nb][3], vhm + off);
                ldsm_x4_trans(b_lo[nb][0], b_lo[nb][1], b_lo[nb][2], b_lo[nb][3], vlm + off);
            }
#pragma unroll
            for (int mi = 0; mi < 2; mi++)
#pragma unroll
                for (int nj = 0; nj < 4; nj++) {
                    int nb = nj >> 1, sel = nj & 1;
                    unsigned bh2[2] = {b_hi[nb][sel * 2], b_hi[nb][sel * 2 + 1]};
                    mma16816(acc[mi][nj], a_hi[mi], bh2);
                }
#pragma unroll
            for (int mi = 0; mi < 2; mi++)
#pragma unroll
                for (int nj = 0; nj < 4; nj++) {
                    int nb = nj >> 1, sel = nj & 1;
                    unsigned bl2[2] = {b_lo[nb][sel * 2], b_lo[nb][sel * 2 + 1]};
                    mma16816(acc[mi][nj], a_hi[mi], bl2);
                }
#pragma unroll
            for (int mi = 0; mi < 2; mi++)
#pragma unroll
                for (int nj = 0; nj < 4; nj++) {
                    int nb = nj >> 1, sel = nj & 1;
                    unsigned bh2[2] = {b_hi[nb][sel * 2], b_hi[nb][sel * 2 + 1]};
                    mma16816(acc[mi][nj], a_lo[mi], bh2);
                }
        }
    }

    const int r0 = lane >> 2, c0 = (lane & 3) * 2;
#pragma unroll
    for (int mi = 0; mi < 2; mi++)
#pragma unroll
        for (int hf = 0; hf < 2; hf++) {
            int ii = i0 + wm + mi * 16 + r0 + hf * 8;
#pragma unroll
            for (int nj = 0; nj < 4; nj++) {
                int dd = wn + nj * 8 + c0;
                float x = acc[mi][nj][hf * 2 + 0];
                float y = acc[mi][nj][hf * 2 + 1];
                unsigned hu, lu;
                split_pack(x, y, hu, lu);
                size_t o = ((size_t)bh_ * S + ii) * DK + dd;
                *(unsigned*)&ch[o] = hu;
                *(unsigned*)&cl[o] = lu;
            }
        }
}

// ---------------------------------------------------------------------------
// Launch (752us config)
// ---------------------------------------------------------------------------
extern "C" void kernel_launch(void* const* d_in, const int* in_sizes, int n_in,
                              void* d_out, int out_size) {
    const float* Q  = (const float*)d_in[0];
    const float* K  = (const float*)d_in[1];
    const float* V  = (const float*)d_in[2];
    const float* Wq = (const float*)d_in[4];
    const float* bq = (const float*)d_in[5];
    const float* Wk = (const float*)d_in[6];
    const float* bk = (const float*)d_in[7];
    const float* Wv = (const float*)d_in[8];
    const float* bv = (const float*)d_in[9];
    const float* Wo = (const float*)d_in[10];
    const float* bo = (const float*)d_in[11];

    cudaFuncSetAttribute(mm_gemm, cudaFuncAttributeMaxDynamicSharedMemorySize,
                         MM_SMEM_BYTES);
    cudaFuncSetAttribute(scores_kernel, cudaFuncAttributeMaxDynamicSharedMemorySize,
                         SC_SMEM_BYTES);
    cudaFuncSetAttribute(ctx_kernel, cudaFuncAttributeMaxDynamicSharedMemorySize,
                         CTX_SMEM_BYTES);

#define SYM(p, s) cudaGetSymbolAddress((void**)&p, s)
    __nv_bfloat16 *xqh, *xql, *xkh, *xkl, *xvh, *xvl;
    __nv_bfloat16 *wqh, *wql, *wkh, *wkl, *wvh, *wvl, *woh, *wol;
    __nv_bfloat16 *qh, *ql, *kh, *kl, *vh, *vl, *ch, *cl;
    SYM(xqh, g_xq_h); SYM(xql, g_xq_l); SYM(xkh, g_xk_h); SYM(xkl, g_xk_l);
    SYM(xvh, g_xv_h); SYM(xvl, g_xv_l);
    SYM(wqh, g_wq_h); SYM(wql, g_wq_l); SYM(wkh, g_wk_h); SYM(wkl, g_wk_l);
    SYM(wvh, g_wv_h); SYM(wvl, g_wv_l); SYM(woh, g_wo_h); SYM(wol, g_wo_l);
    SYM(qh, g_q_h); SYM(ql, g_q_l); SYM(kh, g_k_h); SYM(kl, g_k_l);
    SYM(vh, g_v_h); SYM(vl, g_v_l); SYM(ch, g_ctx_h); SYM(cl, g_ctx_l);

    const size_t OUT_MAIN = (size_t)B * S * D;
    const size_t OUT_ATTN = (size_t)BH * S * S;
    float* outp;
    float* attnp;
    if ((size_t)out_size == OUT_MAIN + OUT_ATTN) {
        outp  = (float*)d_out;
        attnp = (float*)d_out + OUT_MAIN;
    } else if ((size_t)out_size == OUT_ATTN) {
        attnp = (float*)d_out;
        cudaGetSymbolAddress((void**)&outp, g_out_scratch);
    } else {
        outp = (float*)d_out;
        cudaGetSymbolAddress((void**)&attnp, g_attn_scratch);
    }

    const int NX = MP * D, NW = D * D;
    conv_kernel<<<NX / 1024, 256>>>(Q, xqh, xql, NX);
    conv_kernel<<<NX / 1024, 256>>>(K, xkh, xkl, NX);
    conv_kernel<<<NX / 1024, 256>>>(V, xvh, xvl, NX);
    conv_kernel<<<NW / 1024, 256>>>(Wq, wqh, wql, NW);
    conv_kernel<<<NW / 1024, 256>>>(Wk, wkh, wkl, NW);
    conv_kernel<<<NW / 1024, 256>>>(Wv, wvh, wvl, NW);
    conv_kernel<<<NW / 1024, 256>>>(Wo, woh, wol, NW);

    dim3 gproj(D / 128, MP / 128);
    mm_gemm<<<gproj, 256, MM_SMEM_BYTES>>>(xqh, xql, wqh, wql, bq, qh, ql, nullptr, 0);
    mm_gemm<<<gproj, 256, MM_SMEM_BYTES>>>(xkh, xkl, wkh, wkl, bk, kh, kl, nullptr, 0);
    mm_gemm<<<gproj, 256, MM_SMEM_BYTES>>>(xvh, xvl, wvh, wvl, bv, vh, vl, nullptr, 0);

    scores_kernel<<<dim3(S / 128, S / 128, BH), 256, SC_SMEM_BYTES>>>(qh, ql, kh, kl, attnp);

    softmax_kernel<<<dim3(S, BH), 256>>>(attnp);

    ctx_kernel<<<dim3(1, S / 128, BH), 256, CTX_SMEM_BYTES>>>(attnp, vh, vl, ch, cl);

    mm_gemm<<<gproj, 256, MM_SMEM_BYTES>>>(ch, cl, woh, wol, bo, nullptr, nullptr, outp, 1);
}